// round 8
// baseline (speedup 1.0000x reference)
#include <cuda_runtime.h>
#include <math.h>

#define NB    4      // batch
#define S     363    // sinogram length / recon grid
#define A     180    // angles
#define A2    90     // angles per backproject half
#define W     256    // output size
#define RP    364    // table row entries, k in [0,363]
#define NSTR  (A * RP)               // per-batch stride in float2

// tab[na][k] = (mid_k, delta_k), delta_k = p[k]-p[k-1], mid_k = p[k-1]+0.5*delta
// with p[-1] = p[363] = 0. Interp at q (=pos+1, floor k): mid + (w-0.5)*delta.
__device__ float2 g_tab[NB * NSTR];
// angle-half partial sums, layout matches out: [half][n][yy][xx]
__device__ float g_part[2][NB * W * W];

// One block per (n, a) column. Spatial ramp-filter convolution; each thread
// computes the output PAIR (2t, 2t+1) so each tap side is one aligned LDS.64
// (odd left-pad 363 makes 363 + 2t +- d even for odd d).
__global__ __launch_bounds__(384) void ramp_filter_kernel(const float* __restrict__ x) {
    const int na = blockIdx.x;
    const int n  = na / A;
    const int a  = na - n * A;

    __shared__ float xsp[1090];   // [0,363) zeros | [363,726) data | [726,1090) zeros
    __shared__ float ps[S + 2];   // p[-1..363], zero-padded ends

    const int t = threadIdx.x;
    // zero whole buffer, then fill data region
    for (int i = t; i < 1090; i += 384) xsp[i] = 0.0f;
    if (t < 2) ps[t * 364] = 0.0f;            // ps[0]=p[-1]=0, ps[364]=p[363]=0
    __syncthreads();
    // input layout: [n][1][s][a], a fastest
    for (int s = t; s < S; s += 384)
        xsp[363 + s] = x[(n * S + s) * A + a];
    __syncthreads();

    if (t < 182) {                            // outputs s0=2t, s1=2t+1
        const float2* xs2 = (const float2*)xsp;
        float acc0 = 0.5f * xsp[363 + 2 * t];
        float acc1 = 0.5f * xsp[363 + 2 * t + 1];
        #pragma unroll
        for (int j = 0; j < 181; ++j) {
            const int d = 2 * j + 1;
            const float h = -2.0f / ((float)(M_PI * M_PI) * (float)d * (float)d);
            const float2 l = xs2[(363 - d) / 2 + t];  // (x[2t-d], x[2t-d+1])
            const float2 r = xs2[(363 + d) / 2 + t];  // (x[2t+d], x[2t+d+1])
            acc0 = fmaf(l.x + r.x, h, acc0);
            acc1 = fmaf(l.y + r.y, h, acc1);
        }
        ps[1 + 2 * t] = acc0;
        if (2 * t + 1 < S) ps[2 + 2 * t] = acc1;
    }
    __syncthreads();

    float2* gr = g_tab + (size_t)na * RP;
    if (t < RP) {                             // k = t in [0, 363]
        const float p0 = ps[t];               // p[k-1]
        const float p1 = ps[t + 1];           // p[k]
        const float d  = p1 - p0;
        gr[t] = make_float2(fmaf(0.5f, d, p0), d);
    }
}

#define CH 3                     // angles per pipeline chunk (90/3 = 30, even)
#define NCHUNK (A2 / CH)
#define MAGICF 12582912.0f       // 2^23 + 2^22
#define MAGICI 0x4B400000

// grid (W, 2): one block = one output row x one angle-half; all 4 batches
// fused per thread. qp = xf*cos - yf*sin + 181.5; k = round(qp) via magic,
// t = qp - k in [-0.5,0.5]; value = mid[k] + t*delta[k].
__global__ __launch_bounds__(256) void backproject_kernel() {
    const int yy = blockIdx.x;
    const int hf = blockIdx.y;
    const int xx = threadIdx.x;
    const int abase = hf * A2;

    __shared__ float2 scb[A2];   // (cos, 181.5 - yf*sin) for angle abase+t

    const float yf = (float)(yy - 128);
    if (threadIdx.x < A2) {
        float sn, cs;
        sincosf((float)(abase + threadIdx.x) * (float)(M_PI / 180.0), &sn, &cs);
        scb[threadIdx.x] = make_float2(cs, fmaf(-yf, sn, 181.5f));
    }
    __syncthreads();

    const float xf = (float)(xx - 128);
    const float2* __restrict__ tb = g_tab + (size_t)abase * RP;

    float accm0 = 0.f, accm1 = 0.f, accm2 = 0.f, accm3 = 0.f;
    float accd0 = 0.f, accd1 = 0.f, accd2 = 0.f, accd3 = 0.f;

    float2 va[CH * NB], vb[CH * NB];
    float  wa[CH], wb[CH];

    #define LOADC(c, vv, ww)                                                  \
        {                                                                     \
            const int a0 = (c) * CH;                                          \
            _Pragma("unroll")                                                 \
            for (int k = 0; k < CH; ++k) {                                    \
                const float2 cb = scb[a0 + k];                                \
                const float qp = fmaf(xf, cb.x, cb.y);   /* q - 0.5 */        \
                const float f  = qp + MAGICF;                                 \
                const float il = f - MAGICF;             /* round(qp) */      \
                ww[k] = qp - il;                         /* in [-.5,.5] */    \
                const int i = __float_as_int(f) - MAGICI;                     \
                const float2* p = tb + (a0 + k) * RP + i;                     \
                _Pragma("unroll")                                             \
                for (int n = 0; n < NB; ++n)                                  \
                    vv[k * NB + n] = __ldg(p + n * NSTR);                     \
            }                                                                 \
        }

    #define ACCC(vv, ww)                                                      \
        {                                                                     \
            _Pragma("unroll")                                                 \
            for (int k = 0; k < CH; ++k) {                                    \
                accm0 += vv[k * NB + 0].x;                                    \
                accd0 = fmaf(ww[k], vv[k * NB + 0].y, accd0);                 \
                accm1 += vv[k * NB + 1].x;                                    \
                accd1 = fmaf(ww[k], vv[k * NB + 1].y, accd1);                 \
                accm2 += vv[k * NB + 2].x;                                    \
                accd2 = fmaf(ww[k], vv[k * NB + 2].y, accd2);                 \
                accm3 += vv[k * NB + 3].x;                                    \
                accd3 = fmaf(ww[k], vv[k * NB + 3].y, accd3);                 \
            }                                                                 \
        }

    LOADC(0, va, wa)
    LOADC(1, vb, wb)
    #pragma unroll 1
    for (int c = 0; c + 2 < NCHUNK; c += 2) {
        ACCC(va, wa)
        LOADC(c + 2, va, wa)
        ACCC(vb, wb)
        LOADC(c + 3, vb, wb)
    }
    ACCC(va, wa)
    ACCC(vb, wb)

    #undef LOADC
    #undef ACCC

    float* o = g_part[hf] + (size_t)yy * W + xx;
    o[0 * W * W] = accm0 + accd0;
    o[1 * W * W] = accm1 + accd1;
    o[2 * W * W] = accm2 + accd2;
    o[3 * W * W] = accm3 + accd3;
}

// out = (part0 + part1) * pi/360, fully coalesced float4.
__global__ __launch_bounds__(256) void combine_kernel(float* __restrict__ out) {
    const int i = blockIdx.x * 256 + threadIdx.x;     // float4 index
    const float4 p0 = ((const float4*)g_part[0])[i];
    const float4 p1 = ((const float4*)g_part[1])[i];
    const float sc = (float)(M_PI / 360.0);
    float4 r;
    r.x = (p0.x + p1.x) * sc;
    r.y = (p0.y + p1.y) * sc;
    r.z = (p0.z + p1.z) * sc;
    r.w = (p0.w + p1.w) * sc;
    ((float4*)out)[i] = r;
}

extern "C" void kernel_launch(void* const* d_in, const int* in_sizes, int n_in,
                              void* d_out, int out_size) {
    const float* x = (const float*)d_in[0];
    float* out = (float*)d_out;

    ramp_filter_kernel<<<NB * A, 384>>>(x);
    backproject_kernel<<<dim3(W, 2), 256>>>();
    combine_kernel<<<(NB * W * W / 4) / 256, 256>>>(out);
}